// round 16
// baseline (speedup 1.0000x reference)
#include <cuda_runtime.h>
#include <math.h>

#define T_STEPS 4096
#define H_DIM   2048
#define O_DIM   512

#define RNN_CTAS    128
#define RNN_THREADS 256

#define SENTINEL 0x7f800001u   // NaN payload; tanh(finite) can never produce it

// ---------------- device scratch (allocation-free rule) ----------------
__device__ float g_xp[(size_t)T_STEPS * H_DIM];   // x @ W_ih^T + b_ih + b_hh
__device__ float g_hs[(size_t)T_STEPS * H_DIM];   // all hidden states h_t

// Morally-strong volatile ops for the data-as-flag protocol (R8, proven).
__device__ __forceinline__ uint4 ld_vol_u4(const uint4* p)
{
    uint4 v;
    asm volatile("ld.volatile.global.v4.u32 {%0,%1,%2,%3}, [%4];"
                 : "=r"(v.x), "=r"(v.y), "=r"(v.z), "=r"(v.w)
                 : "l"(p) : "memory");
    return v;
}
__device__ __forceinline__ void st_vol_f32(float* p, float v)
{
    asm volatile("st.volatile.global.f32 [%0], %1;"
                 :: "l"(p), "f"(v) : "memory");
}
__device__ __forceinline__ bool has_sent(uint4 v)
{
    return (v.x == SENTINEL) | (v.y == SENTINEL) |
           (v.z == SENTINEL) | (v.w == SENTINEL);
}

// ---------------- tf32 helpers -----------------------------------------
__device__ __forceinline__ unsigned f2tf32(float f)
{
    unsigned r;
    asm("cvt.rna.tf32.f32 %0, %1;" : "=r"(r) : "f"(f));
    return r;
}
__device__ __forceinline__ void tf32_split(float a, unsigned& hi, unsigned& lo)
{
    hi = f2tf32(a);
    lo = f2tf32(a - __uint_as_float(hi));
}
__device__ __forceinline__ void mma_tf32(float4& d,
    unsigned a0, unsigned a1, unsigned a2, unsigned a3,
    unsigned b0, unsigned b1)
{
    asm("mma.sync.aligned.m16n8k8.row.col.f32.tf32.tf32.f32 "
        "{%0,%1,%2,%3}, {%4,%5,%6,%7}, {%8,%9}, {%0,%1,%2,%3};"
        : "+f"(d.x), "+f"(d.y), "+f"(d.z), "+f"(d.w)
        : "r"(a0), "r"(a1), "r"(a2), "r"(a3), "r"(b0), "r"(b1));
}

// ---------------- sentinel reset (graph-replay safe) -------------------
__global__ void reset_hs_kernel()
{
    size_t i = (size_t)blockIdx.x * blockDim.x + threadIdx.x;
    ((uint4*)g_hs)[i] = make_uint4(SENTINEL, SENTINEL, SENTINEL, SENTINEL);
}

// ---------------- persistent recurrence kernel (R14, unchanged) --------
__global__ void __launch_bounds__(RNN_THREADS, 1)
rnn_kernel(const float* __restrict__ W_hh, const float* __restrict__ h0)
{
    __shared__ __align__(16) float hbuf[2][H_DIM];   // double-buffered h
    const int tid  = threadIdx.x;
    const int lane = tid & 31;
    const int wid  = tid >> 5;                    // 0..7
    const int r0   = blockIdx.x * 16 + wid * 2;   // this warp's two rows
    const bool odd = lane & 1;

    float4 w0[16], w1[16];
    const float4* W0 = (const float4*)(W_hh + (size_t)r0 * H_DIM);
    const float4* W1 = (const float4*)(W_hh + (size_t)(r0 + 1) * H_DIM);
#pragma unroll
    for (int j = 0; j < 16; j++) {
        w0[j] = __ldg(&W0[j * 32 + lane]);
        w1[j] = __ldg(&W1[j * 32 + lane]);
    }

    for (int t = 0; t < T_STEPS; t++) {
        const int buf = t & 1;

        float xpv = 0.f;
        if (lane < 2) {
            xpv = __ldg(&g_xp[(size_t)t * H_DIM + r0 + lane]);
        }

        float4 a4, b4;
        if (t == 0) {
            a4 = __ldg(&((const float4*)h0)[tid]);
            b4 = __ldg(&((const float4*)h0)[tid + RNN_THREADS]);
        } else {
            const uint4* hp = (const uint4*)(g_hs + (size_t)(t - 1) * H_DIM);
            uint4 ua, ub;
            bool da = false, db = false;
            do {
                if (!da) { ua = ld_vol_u4(hp + tid);               da = !has_sent(ua); }
                if (!db) { ub = ld_vol_u4(hp + tid + RNN_THREADS); db = !has_sent(ub); }
            } while (!(da && db));
            a4 = make_float4(__uint_as_float(ua.x), __uint_as_float(ua.y),
                             __uint_as_float(ua.z), __uint_as_float(ua.w));
            b4 = make_float4(__uint_as_float(ub.x), __uint_as_float(ub.y),
                             __uint_as_float(ub.z), __uint_as_float(ub.w));
        }

        ((float4*)hbuf[buf])[tid]               = a4;
        ((float4*)hbuf[buf])[tid + RNN_THREADS] = b4;
        __syncthreads();

        float acc0 = 0.f, acc1 = 0.f;
#pragma unroll
        for (int j = 0; j < 16; j++) {
            float4 h4 = ((const float4*)hbuf[buf])[j * 32 + lane];
            acc0 += w0[j].x * h4.x; acc1 += w1[j].x * h4.x;
            acc0 += w0[j].y * h4.y; acc1 += w1[j].y * h4.y;
            acc0 += w0[j].z * h4.z; acc1 += w1[j].z * h4.z;
            acc0 += w0[j].w * h4.w; acc1 += w1[j].w * h4.w;
        }

        // Joint butterfly reduction (5 levels); even lanes -> s0, odd -> s1.
        float mine  = odd ? acc1 : acc0;
        float other = odd ? acc0 : acc1;
        mine += __shfl_xor_sync(0xffffffffu, other, 1);
#pragma unroll
        for (int off = 2; off < 32; off <<= 1) {
            mine += __shfl_xor_sync(0xffffffffu, mine, off);
        }

        if (lane < 2) {
            float v = tanhf(xpv + mine);
            st_vol_f32(&g_hs[(size_t)t * H_DIM + r0 + lane], v);
        }
    }
}

// ---------------- 3xTF32 tensor-core NT GEMM (both phases) -------------
// C[M,N] = A[M,K] @ B[N,K]^T + bias, fp32 in/out, 3xTF32 decomposition.
// v2: hi/lo split ONCE at tile-load (not per-fragment-per-warp), separate
// hi/lo smem tiles, register prefetch of the next k-tile during MMAs.
// CTA tile 128x64, BK=16; 8 warps 4(m)x2(n); warp tile 32x32.
// PHASE 0: A = param (x),   C = g_xp,  bias = b_ih + b_hh
// PHASE 1: A = g_hs,        C = param, bias = b_lin
#define TBM 128
#define TBN 64
#define TBK 16
#define TPAD 20   // stride 20 floats: lanes (g,tg) -> g*20+tg all-distinct banks

template<int PHASE>
__global__ void __launch_bounds__(256, 2)
gemm_tf32(const float* __restrict__ Ap,
          const float* __restrict__ B,
          const float* __restrict__ bias1,
          const float* __restrict__ bias2,
          float* __restrict__ Cp,
          int M, int N, int K)
{
    __shared__ __align__(16) unsigned AsH[TBM][TPAD], AsL[TBM][TPAD];
    __shared__ __align__(16) unsigned BsH[TBN][TPAD], BsL[TBN][TPAD];

    const float* A = (PHASE == 0) ? Ap   : g_hs;
    float*       C = (PHASE == 0) ? g_xp : Cp;

    const int tid    = threadIdx.x;
    const int lane   = tid & 31;
    const int wid    = tid >> 5;
    const int warp_m = wid & 3;          // m offset warp_m*32
    const int warp_n = wid >> 2;         // n offset warp_n*32
    const int g      = lane >> 2;        // groupID 0..7
    const int tg     = lane & 3;         // threadID_in_group 0..3
    const int m0     = blockIdx.y * TBM;
    const int n0     = blockIdx.x * TBN;

    const int lrow = tid >> 2;           // 0..63
    const int lkq  = tid & 3;            // float4 index within k-tile

    float4 acc_dummy; (void)acc_dummy;
    float4 acc[2][4];
#pragma unroll
    for (int im = 0; im < 2; im++)
#pragma unroll
        for (int in = 0; in < 4; in++)
            acc[im][in] = make_float4(0.f, 0.f, 0.f, 0.f);

    // ---- prefetch tile 0 into registers ----
    float4 pa0, pa1, pbv;
    pa0 = *(const float4*)(A + (size_t)(m0 + lrow) * K + lkq * 4);
    pa1 = *(const float4*)(A + (size_t)(m0 + 64 + lrow) * K + lkq * 4);
    pbv = *(const float4*)(B + (size_t)(n0 + lrow) * K + lkq * 4);

    for (int k0 = 0; k0 < K; k0 += TBK) {
        // ---- split prefetched tile into hi/lo smem ----
        {
            uint4 h, l;
            tf32_split(pa0.x, h.x, l.x); tf32_split(pa0.y, h.y, l.y);
            tf32_split(pa0.z, h.z, l.z); tf32_split(pa0.w, h.w, l.w);
            *(uint4*)&AsH[lrow][lkq * 4] = h;  *(uint4*)&AsL[lrow][lkq * 4] = l;
            tf32_split(pa1.x, h.x, l.x); tf32_split(pa1.y, h.y, l.y);
            tf32_split(pa1.z, h.z, l.z); tf32_split(pa1.w, h.w, l.w);
            *(uint4*)&AsH[64 + lrow][lkq * 4] = h;  *(uint4*)&AsL[64 + lrow][lkq * 4] = l;
            tf32_split(pbv.x, h.x, l.x); tf32_split(pbv.y, h.y, l.y);
            tf32_split(pbv.z, h.z, l.z); tf32_split(pbv.w, h.w, l.w);
            *(uint4*)&BsH[lrow][lkq * 4] = h;  *(uint4*)&BsL[lrow][lkq * 4] = l;
        }
        __syncthreads();

        // ---- prefetch next tile while doing MMAs ----
        if (k0 + TBK < K) {
            pa0 = *(const float4*)(A + (size_t)(m0 + lrow) * K + k0 + TBK + lkq * 4);
            pa1 = *(const float4*)(A + (size_t)(m0 + 64 + lrow) * K + k0 + TBK + lkq * 4);
            pbv = *(const float4*)(B + (size_t)(n0 + lrow) * K + k0 + TBK + lkq * 4);
        }

#pragma unroll
        for (int ks = 0; ks < 2; ks++) {
            const int kb = ks * 8;
            unsigned ah[2][4], al[2][4];
#pragma unroll
            for (int im = 0; im < 2; im++) {
                const int mb = warp_m * 32 + im * 16;
                ah[im][0] = AsH[mb + g][kb + tg];
                ah[im][1] = AsH[mb + g + 8][kb + tg];
                ah[im][2] = AsH[mb + g][kb + tg + 4];
                ah[im][3] = AsH[mb + g + 8][kb + tg + 4];
                al[im][0] = AsL[mb + g][kb + tg];
                al[im][1] = AsL[mb + g + 8][kb + tg];
                al[im][2] = AsL[mb + g][kb + tg + 4];
                al[im][3] = AsL[mb + g + 8][kb + tg + 4];
            }
            unsigned bh[4][2], bl[4][2];
#pragma unroll
            for (int in = 0; in < 4; in++) {
                const int nb = warp_n * 32 + in * 8;
                bh[in][0] = BsH[nb + g][kb + tg];
                bh[in][1] = BsH[nb + g][kb + tg + 4];
                bl[in][0] = BsL[nb + g][kb + tg];
                bl[in][1] = BsL[nb + g][kb + tg + 4];
            }
#pragma unroll
            for (int im = 0; im < 2; im++)
#pragma unroll
                for (int in = 0; in < 4; in++) {
                    // same term order as the validated R15 kernel
                    mma_tf32(acc[im][in], al[im][0], al[im][1], al[im][2], al[im][3],
                             bh[in][0], bh[in][1]);
                    mma_tf32(acc[im][in], ah[im][0], ah[im][1], ah[im][2], ah[im][3],
                             bl[in][0], bl[in][1]);
                    mma_tf32(acc[im][in], ah[im][0], ah[im][1], ah[im][2], ah[im][3],
                             bh[in][0], bh[in][1]);
                }
        }
        __syncthreads();
    }

    // Epilogue: bias + store (same mapping as validated R15 kernel).
#pragma unroll
    for (int in = 0; in < 4; in++) {
        const int nb = n0 + warp_n * 32 + in * 8 + 2 * tg;
        float b0 = __ldg(&bias1[nb]);
        float b1 = __ldg(&bias1[nb + 1]);
        if (bias2) { b0 += __ldg(&bias2[nb]); b1 += __ldg(&bias2[nb + 1]); }
#pragma unroll
        for (int im = 0; im < 2; im++) {
            const int mb = m0 + warp_m * 32 + im * 16 + g;
            float2 lo = make_float2(acc[im][in].x + b0, acc[im][in].y + b1);
            float2 hi = make_float2(acc[im][in].z + b0, acc[im][in].w + b1);
            *(float2*)(C + (size_t)mb * N + nb)       = lo;
            *(float2*)(C + (size_t)(mb + 8) * N + nb) = hi;
        }
    }
}

// ---------------- launch ------------------------------------------------
extern "C" void kernel_launch(void* const* d_in, const int* in_sizes, int n_in,
                              void* d_out, int out_size)
{
    const float* x     = (const float*)d_in[0];  // (T,1,H)
    const float* W_ih  = (const float*)d_in[1];  // (H,H)
    const float* W_hh  = (const float*)d_in[2];  // (H,H)
    const float* b_ih  = (const float*)d_in[3];  // (H)
    const float* b_hh  = (const float*)d_in[4];  // (H)
    const float* W_lin = (const float*)d_in[5];  // (O,H)
    const float* b_lin = (const float*)d_in[6];  // (O)
    const float* h0    = (const float*)d_in[7];  // (1,1,H)
    float* out = (float*)d_out;                  // (T,1,O)

    // Reset g_hs to sentinel (must precede rnn_kernel every launch/replay).
    reset_hs_kernel<<<(T_STEPS * H_DIM / 4) / 256, 256>>>();

    // Phase 1: g_xp = x @ W_ih^T + b_ih + b_hh   (3xTF32 tensor cores)
    gemm_tf32<0><<<dim3(H_DIM / TBN, T_STEPS / TBM), 256>>>(
        x, W_ih, b_ih, b_hh, nullptr, T_STEPS, H_DIM, H_DIM);

    // Phase 2: sequential recurrence -> g_hs
    rnn_kernel<<<RNN_CTAS, RNN_THREADS>>>(W_hh, h0);

    // Phase 3: out = g_hs @ W_lin^T + b_lin   (3xTF32 tensor cores)
    gemm_tf32<1><<<dim3(O_DIM / TBN, T_STEPS / TBM), 256>>>(
        nullptr, W_lin, b_lin, nullptr, out, T_STEPS, O_DIM, H_DIM);
}